// round 1
// baseline (speedup 1.0000x reference)
#include <cuda_runtime.h>
#include <math.h>

#define N_IMG 16
#define HH 512
#define WW 512
#define HW (HH*WW)
#define NPIX (N_IMG*HW)
#define GRIDN 8
#define TH 64
#define TW 64
#define AREA (TH*TW)
#define NBINS 256
#define NTILES (GRIDN*GRIDN)

#define LAB_EPS (216.0f/24389.0f)
#define LAB_KAPPA (24389.0f/27.0f)

// ---------------- scratch (no allocations allowed) ----------------
__device__ float g_L[NPIX];
__device__ float g_a[NPIX];
__device__ float g_b[NPIX];
__device__ unsigned char g_lint[NPIX];
__device__ unsigned int g_minbits[N_IMG];
__device__ unsigned int g_maxbits[N_IMG];
__device__ int   g_tilehist[N_IMG*NTILES*NBINS];
__device__ float g_tilelut [N_IMG*NTILES*NBINS];
__device__ float g_eqlut   [N_IMG*NBINS];

// ---------------- helpers ----------------
__device__ __forceinline__ float srgb2lin(float c) {
    return (c <= 0.04045f) ? (c / 12.92f) : powf((c + 0.055f) / 1.055f, 2.4f);
}
__device__ __forceinline__ float lin2srgb(float c) {
    c = fmaxf(c, 0.0f);
    return (c <= 0.0031308f) ? (c * 12.92f) : (1.055f * powf(c, 1.0f/2.4f) - 0.055f);
}
__device__ __forceinline__ float labf(float x) {
    return (x > LAB_EPS) ? cbrtf(x) : (LAB_KAPPA * x + 16.0f) / 116.0f;
}
__device__ __forceinline__ float labfinv(float f) {
    float f3 = f * f * f;
    return (f3 > LAB_EPS) ? f3 : (116.0f * f - 16.0f) / LAB_KAPPA;
}
__device__ __forceinline__ float clamp01(float c) {
    return fminf(fmaxf(c, 0.0f), 1.0f);
}

__device__ __forceinline__ void lab2rgb255(float l255, float a, float b,
                                           float& r, float& g, float& bl) {
    float L  = l255 * (100.0f / 255.0f);
    float fy = (L + 16.0f) / 116.0f;
    float fx = fy + a / 500.0f;
    float fz = fy - b / 200.0f;
    float X = labfinv(fx) * 0.95047f;
    float Y = labfinv(fy) * 1.0f;
    float Z = labfinv(fz) * 1.08883f;
    float rl =  3.2404542f*X - 1.5371385f*Y - 0.4985314f*Z;
    float gl = -0.9692660f*X + 1.8760108f*Y + 0.0415560f*Z;
    float bb =  0.0556434f*X - 0.2040259f*Y + 1.0572252f*Z;
    r  = 255.0f * clamp01(lin2srgb(rl));
    g  = 255.0f * clamp01(lin2srgb(gl));
    bl = 255.0f * clamp01(lin2srgb(bb));
}

// ---------------- K0: init scratch ----------------
__global__ void k_init() {
    int i = blockIdx.x * blockDim.x + threadIdx.x;
    if (i < N_IMG*NTILES*NBINS) g_tilehist[i] = 0;
    if (i < N_IMG) {
        g_minbits[i] = 0x7F7FFFFFu; // FLT_MAX
        g_maxbits[i] = 0u;          // 0.0f (L >= 0)
    }
}

// ---------------- K1: RGB -> Lab + per-image min/max of L ----------------
__global__ void k_lab(const float* __restrict__ x) {
    int p = blockIdx.x * blockDim.x + threadIdx.x;
    int n  = p / HW;
    int hw = p - n * HW;
    const float* img = x + (size_t)n * 3 * HW;
    float r = img[hw], g = img[hw + HW], b = img[hw + 2*HW];

    float lr = srgb2lin(r), lg = srgb2lin(g), lb = srgb2lin(b);
    float X = (0.4124564f*lr + 0.3575761f*lg + 0.1804375f*lb) / 0.95047f;
    float Y = (0.2126729f*lr + 0.7151522f*lg + 0.0721750f*lb) / 1.0f;
    float Z = (0.0193339f*lr + 0.1191920f*lg + 0.9503041f*lb) / 1.08883f;
    float fx = labf(X), fy = labf(Y), fz = labf(Z);
    float L = 116.0f * fy - 16.0f;
    g_L[p] = L;
    g_a[p] = 500.0f * (fx - fy);
    g_b[p] = 200.0f * (fy - fz);

    // block min/max reduction (block entirely inside one image: HW%256==0)
    float vmin = L, vmax = L;
    #pragma unroll
    for (int o = 16; o > 0; o >>= 1) {
        vmin = fminf(vmin, __shfl_down_sync(0xFFFFFFFFu, vmin, o));
        vmax = fmaxf(vmax, __shfl_down_sync(0xFFFFFFFFu, vmax, o));
    }
    __shared__ float wmin[8], wmax[8];
    int lane = threadIdx.x & 31, warp = threadIdx.x >> 5;
    if (lane == 0) { wmin[warp] = vmin; wmax[warp] = vmax; }
    __syncthreads();
    if (threadIdx.x == 0) {
        float bmin = wmin[0], bmax = wmax[0];
        #pragma unroll
        for (int i = 1; i < 8; i++) {
            bmin = fminf(bmin, wmin[i]);
            bmax = fmaxf(bmax, wmax[i]);
        }
        atomicMin(&g_minbits[n], __float_as_uint(bmin));
        atomicMax(&g_maxbits[n], __float_as_uint(bmax));
    }
}

// ---------------- K2: quantize L + per-tile histograms ----------------
// one block per tile: blockIdx = n*64 + tile, 256 threads
__global__ void k_quant_hist() {
    int blk = blockIdx.x;
    int n = blk >> 6;
    int t = blk & 63;
    int ty = t >> 3, tx = t & 7;

    __shared__ int sh[NBINS];
    sh[threadIdx.x] = 0;
    __syncthreads();

    float lmin = __uint_as_float(g_minbits[n]);
    float lmax = __uint_as_float(g_maxbits[n]);
    float denom = lmax - lmin + 1e-6f;

    int base = n * HW + (ty * TH) * WW + tx * TW;
    for (int i = threadIdx.x; i < AREA; i += 256) {
        int hh = i >> 6, wloc = i & 63;
        int p = base + hh * WW + wloc;
        float l255 = (g_L[p] - lmin) / denom * 255.0f;
        int v = (int)rintf(l255);
        v = min(max(v, 0), 255);
        g_lint[p] = (unsigned char)v;
        atomicAdd(&sh[v], 1);
    }
    __syncthreads();
    g_tilehist[blk * NBINS + threadIdx.x] = sh[threadIdx.x];
}

// ---------------- K3a: global equalize LUT per image ----------------
__global__ void k_eqlut() {
    int n = blockIdx.x;
    int t = threadIdx.x;
    int s = 0;
    for (int tt = 0; tt < NTILES; tt++)
        s += g_tilehist[(n * NTILES + tt) * NBINS + t];
    __shared__ float sc[NBINS];
    sc[t] = (float)s;
    for (int off = 1; off < NBINS; off <<= 1) {
        __syncthreads();
        float add = (t >= off) ? sc[t - off] : 0.0f;
        __syncthreads();
        sc[t] += add;
    }
    __syncthreads();
    g_eqlut[n * NBINS + t] = rintf(sc[t] * (255.0f / (float)HW));
}

// ---------------- K3b: CLAHE tile LUTs ----------------
__global__ void k_tilelut() {
    int blk = blockIdx.x;        // n*64 + tile
    int t = threadIdx.x;
    float hv = (float)g_tilehist[blk * NBINS + t];
    const float limit = 32.0f;   // max(2.0*4096/256, 1.0)
    float clipped = fminf(hv, limit);
    float exc = hv - clipped;

    __shared__ float red[NBINS];
    red[t] = exc;
    for (int off = 128; off > 0; off >>= 1) {
        __syncthreads();
        if (t < off) red[t] += red[t + off];
    }
    __syncthreads();
    float excess = red[0];
    __syncthreads();

    // inclusive scan of clipped
    red[t] = clipped;
    for (int off = 1; off < NBINS; off <<= 1) {
        __syncthreads();
        float add = (t >= off) ? red[t - off] : 0.0f;
        __syncthreads();
        red[t] += add;
    }
    __syncthreads();
    float cum = red[t] + (float)(t + 1) * (excess / (float)NBINS);
    g_tilelut[blk * NBINS + t] = rintf(cum * (255.0f / (float)AREA));
}

// ---------------- K4: reconstruct both outputs ----------------
__global__ void k_out(float* __restrict__ out) {
    int p = blockIdx.x * blockDim.x + threadIdx.x;
    int n  = p / HW;
    int hw = p - n * HW;
    int h = hw >> 9, w = hw & 511;

    int v = (int)g_lint[p];
    float a = g_a[p], b = g_b[p];

    // equalize
    float eq_l = g_eqlut[n * NBINS + v];

    // clahe bilinear of tile LUTs
    float cy = fminf(fmaxf(((float)h + 0.5f) / (float)TH - 0.5f, 0.0f), (float)(GRIDN - 1));
    float cx = fminf(fmaxf(((float)w + 0.5f) / (float)TW - 0.5f, 0.0f), (float)(GRIDN - 1));
    int y0 = min((int)floorf(cy), GRIDN - 2);
    int x0 = min((int)floorf(cx), GRIDN - 2);
    float wy = cy - (float)y0;
    float wx = cx - (float)x0;
    const float* lb = g_tilelut + (size_t)n * NTILES * NBINS;
    float v00 = lb[((y0    )*GRIDN + x0    ) * NBINS + v];
    float v01 = lb[((y0    )*GRIDN + x0 + 1) * NBINS + v];
    float v10 = lb[((y0 + 1)*GRIDN + x0    ) * NBINS + v];
    float v11 = lb[((y0 + 1)*GRIDN + x0 + 1) * NBINS + v];
    float top = v00 * (1.0f - wx) + v01 * wx;
    float bot = v10 * (1.0f - wx) + v11 * wx;
    float cl_l = top * (1.0f - wy) + bot * wy;

    float r0, g0, b0, r1, g1, b1;
    lab2rgb255(eq_l, a, b, r0, g0, b0);
    lab2rgb255(cl_l, a, b, r1, g1, b1);

    size_t base0 = (size_t)n * 3 * HW + hw;            // equalize output
    size_t base1 = (size_t)NPIX * 3 + base0;           // clahe output
    out[base0]          = r0;
    out[base0 + HW]     = g0;
    out[base0 + 2*HW]   = b0;
    out[base1]          = r1;
    out[base1 + HW]     = g1;
    out[base1 + 2*HW]   = b1;
}

// ---------------- launch ----------------
extern "C" void kernel_launch(void* const* d_in, const int* in_sizes, int n_in,
                              void* d_out, int out_size) {
    const float* x = (const float*)d_in[0];
    float* out = (float*)d_out;
    (void)in_sizes; (void)n_in; (void)out_size;

    k_init<<<(N_IMG*NTILES*NBINS + 255) / 256, 256>>>();
    k_lab<<<NPIX / 256, 256>>>(x);
    k_quant_hist<<<N_IMG * NTILES, 256>>>();
    k_eqlut<<<N_IMG, NBINS>>>();
    k_tilelut<<<N_IMG * NTILES, NBINS>>>();
    k_out<<<NPIX / 256, 256>>>(out);
}

// round 2
// speedup vs baseline: 1.9258x; 1.9258x over previous
#include <cuda_runtime.h>
#include <math.h>

#define N_IMG 16
#define HH 512
#define WW 512
#define HW (HH*WW)
#define NPIX (N_IMG*HW)
#define GRIDN 8
#define TH 64
#define TW 64
#define AREA (TH*TW)
#define NBINS 256
#define NTILES (GRIDN*GRIDN)

#define LAB_EPS (216.0f/24389.0f)
#define LAB_KAPPA (24389.0f/27.0f)

// ---------------- scratch (no allocations allowed) ----------------
__device__ float g_L[NPIX];
__device__ float g_a[NPIX];
__device__ float g_b[NPIX];
__device__ unsigned char g_lint[NPIX];
__device__ unsigned int g_minbits[N_IMG];
__device__ unsigned int g_maxbits[N_IMG];
__device__ int   g_tilehist[N_IMG*NTILES*NBINS];
__device__ float g_tilelut [N_IMG*NTILES*NBINS];
__device__ float g_eqlut   [N_IMG*NBINS];

// ---------------- helpers ----------------
// accurate paths (used where quantization boundaries matter)
__device__ __forceinline__ float srgb2lin_acc(float c) {
    return (c <= 0.04045f) ? (c * (1.0f/12.92f)) : powf((c + 0.055f) * (1.0f/1.055f), 2.4f);
}
__device__ __forceinline__ float labf_acc(float x) {
    return (x > LAB_EPS) ? cbrtf(x) : (LAB_KAPPA * x + 16.0f) * (1.0f/116.0f);
}
// fast path (continuous output math only)
__device__ __forceinline__ float lin2srgb_fast(float c) {
    c = fmaxf(c, 0.0f);
    return (c <= 0.0031308f) ? (c * 12.92f)
                             : (1.055f * __powf(c, 1.0f/2.4f) - 0.055f);
}
__device__ __forceinline__ float labfinv(float f) {
    float f3 = f * f * f;
    return (f3 > LAB_EPS) ? f3 : (116.0f * f - 16.0f) * (1.0f/LAB_KAPPA);
}
__device__ __forceinline__ float clamp01(float c) {
    return fminf(fmaxf(c, 0.0f), 1.0f);
}

__device__ __forceinline__ void lab2rgb255(float l255, float a, float b,
                                           float& r, float& g, float& bl) {
    float L  = l255 * (100.0f / 255.0f);
    float fy = (L + 16.0f) * (1.0f/116.0f);
    float fx = fy + a * (1.0f/500.0f);
    float fz = fy - b * (1.0f/200.0f);
    float X = labfinv(fx) * 0.95047f;
    float Y = labfinv(fy);
    float Z = labfinv(fz) * 1.08883f;
    float rl =  3.2404542f*X - 1.5371385f*Y - 0.4985314f*Z;
    float gl = -0.9692660f*X + 1.8760108f*Y + 0.0415560f*Z;
    float bb =  0.0556434f*X - 0.2040259f*Y + 1.0572252f*Z;
    r  = 255.0f * clamp01(lin2srgb_fast(rl));
    g  = 255.0f * clamp01(lin2srgb_fast(gl));
    bl = 255.0f * clamp01(lin2srgb_fast(bb));
}

// 256-element inclusive scan (256 threads), shfl based
__device__ __forceinline__ float inclusive_scan_256(float v, float* ws8) {
    int lane = threadIdx.x & 31, warp = threadIdx.x >> 5;
    #pragma unroll
    for (int o = 1; o < 32; o <<= 1) {
        float t = __shfl_up_sync(0xFFFFFFFFu, v, o);
        if (lane >= o) v += t;
    }
    if (lane == 31) ws8[warp] = v;
    __syncthreads();
    if (warp == 0 && lane < 8) {
        float s = ws8[lane];
        #pragma unroll
        for (int o = 1; o < 8; o <<= 1) {
            float t = __shfl_up_sync(0xFFu, s, o);
            if (lane >= o) s += t;
        }
        ws8[lane] = s;
    }
    __syncthreads();
    if (warp > 0) v += ws8[warp - 1];
    return v;
}

// ---------------- K0: init min/max seeds ----------------
__global__ void k_init() {
    int i = threadIdx.x;
    if (i < N_IMG) {
        g_minbits[i] = 0x7F7FFFFFu; // FLT_MAX
        g_maxbits[i] = 0u;          // 0.0f (L >= 0)
    }
}

// ---------------- K1: RGB -> Lab + per-image min/max of L (4 px/thread) ----------------
__global__ void k_lab(const float* __restrict__ x) {
    int t  = blockIdx.x * blockDim.x + threadIdx.x;
    int p4 = t * 4;
    int n  = p4 / HW;
    int hw = p4 - n * HW;
    const float* img = x + (size_t)n * 3 * HW;
    float4 R = *(const float4*)(img + hw);
    float4 G = *(const float4*)(img + HW + hw);
    float4 B = *(const float4*)(img + 2*HW + hw);

    float4 Lo, Ao, Bo;
    float vmin =  1e30f, vmax = -1e30f;
    #pragma unroll
    for (int k = 0; k < 4; k++) {
        float r = (k==0)?R.x:(k==1)?R.y:(k==2)?R.z:R.w;
        float g = (k==0)?G.x:(k==1)?G.y:(k==2)?G.z:G.w;
        float b = (k==0)?B.x:(k==1)?B.y:(k==2)?B.z:B.w;
        float lr = srgb2lin_acc(r), lg = srgb2lin_acc(g), lb = srgb2lin_acc(b);
        float X = (0.4124564f*lr + 0.3575761f*lg + 0.1804375f*lb) * (1.0f/0.95047f);
        float Y = (0.2126729f*lr + 0.7151522f*lg + 0.0721750f*lb);
        float Z = (0.0193339f*lr + 0.1191920f*lg + 0.9503041f*lb) * (1.0f/1.08883f);
        float fx = labf_acc(X), fy = labf_acc(Y), fz = labf_acc(Z);
        float L = 116.0f * fy - 16.0f;
        float a = 500.0f * (fx - fy);
        float bb = 200.0f * (fy - fz);
        if (k==0){Lo.x=L;Ao.x=a;Bo.x=bb;} else if(k==1){Lo.y=L;Ao.y=a;Bo.y=bb;}
        else if (k==2){Lo.z=L;Ao.z=a;Bo.z=bb;} else {Lo.w=L;Ao.w=a;Bo.w=bb;}
        vmin = fminf(vmin, L); vmax = fmaxf(vmax, L);
    }
    *(float4*)(g_L + p4) = Lo;
    *(float4*)(g_a + p4) = Ao;
    *(float4*)(g_b + p4) = Bo;

    #pragma unroll
    for (int o = 16; o > 0; o >>= 1) {
        vmin = fminf(vmin, __shfl_down_sync(0xFFFFFFFFu, vmin, o));
        vmax = fmaxf(vmax, __shfl_down_sync(0xFFFFFFFFu, vmax, o));
    }
    __shared__ float wmin[8], wmax[8];
    int lane = threadIdx.x & 31, warp = threadIdx.x >> 5;
    if (lane == 0) { wmin[warp] = vmin; wmax[warp] = vmax; }
    __syncthreads();
    if (threadIdx.x == 0) {
        float bmin = wmin[0], bmax = wmax[0];
        #pragma unroll
        for (int i = 1; i < 8; i++) {
            bmin = fminf(bmin, wmin[i]);
            bmax = fmaxf(bmax, wmax[i]);
        }
        atomicMin(&g_minbits[n], __float_as_uint(bmin));
        atomicMax(&g_maxbits[n], __float_as_uint(bmax));
    }
}

// ---------------- K2: quantize L + per-tile histograms ----------------
// one block per tile: blockIdx = n*64 + tile, 256 threads, 4 px/iter (float4)
__global__ void k_quant_hist() {
    int blk = blockIdx.x;
    int n = blk >> 6;
    int t = blk & 63;
    int ty = t >> 3, tx = t & 7;

    __shared__ int sh[NBINS];
    sh[threadIdx.x] = 0;
    __syncthreads();

    float lmin = __uint_as_float(g_minbits[n]);
    float lmax = __uint_as_float(g_maxbits[n]);
    float scale = 255.0f / (lmax - lmin + 1e-6f);

    int base = n * HW + (ty * TH) * WW + tx * TW;
    #pragma unroll
    for (int it = 0; it < 4; it++) {
        int i = threadIdx.x + it * 256;          // 0..1023 float4 chunks
        int row = i >> 4, c16 = i & 15;
        int p = base + row * WW + c16 * 4;
        float4 L4 = *(const float4*)(g_L + p);
        int v0 = min(max((int)rintf((L4.x - lmin) * scale), 0), 255);
        int v1 = min(max((int)rintf((L4.y - lmin) * scale), 0), 255);
        int v2 = min(max((int)rintf((L4.z - lmin) * scale), 0), 255);
        int v3 = min(max((int)rintf((L4.w - lmin) * scale), 0), 255);
        uchar4 u = make_uchar4((unsigned char)v0, (unsigned char)v1,
                               (unsigned char)v2, (unsigned char)v3);
        *(uchar4*)(g_lint + p) = u;
        atomicAdd(&sh[v0], 1);
        atomicAdd(&sh[v1], 1);
        atomicAdd(&sh[v2], 1);
        atomicAdd(&sh[v3], 1);
    }
    __syncthreads();
    g_tilehist[blk * NBINS + threadIdx.x] = sh[threadIdx.x];
}

// ---------------- K3: both LUT families in one kernel ----------------
// blocks [0, N_IMG*NTILES): CLAHE tile LUTs;  [N_IMG*NTILES, +N_IMG): equalize LUTs
__global__ void k_luts() {
    __shared__ float ws8[8];
    __shared__ float totc;
    int blk = blockIdx.x;
    int t = threadIdx.x;
    if (blk < N_IMG * NTILES) {
        float hv = (float)g_tilehist[blk * NBINS + t];
        float clipped = fminf(hv, 32.0f);       // max(2.0*4096/256, 1.0)
        float cum = inclusive_scan_256(clipped, ws8);
        if (t == 255) totc = cum;
        __syncthreads();
        float excess = (float)AREA - totc;      // hist sums to exactly AREA
        float val = cum + (float)(t + 1) * (excess * (1.0f/256.0f));
        g_tilelut[blk * NBINS + t] = rintf(val * (255.0f / (float)AREA));
    } else {
        int n = blk - N_IMG * NTILES;
        int s = 0;
        #pragma unroll
        for (int tt = 0; tt < NTILES; tt++)
            s += g_tilehist[(n * NTILES + tt) * NBINS + t];
        float cum = inclusive_scan_256((float)s, ws8);
        g_eqlut[n * NBINS + t] = rintf(cum * (255.0f / (float)HW));
    }
}

// ---------------- K4: reconstruct both outputs (4 px/thread) ----------------
__global__ void k_out(float* __restrict__ out) {
    int t  = blockIdx.x * blockDim.x + threadIdx.x;
    int p4 = t * 4;
    int n  = p4 / HW;
    int hw = p4 - n * HW;
    int h = hw >> 9, w0 = hw & 511;

    uchar4 v4 = *(const uchar4*)(g_lint + p4);
    float4 A4 = *(const float4*)(g_a + p4);
    float4 B4 = *(const float4*)(g_b + p4);

    float cy = fminf(fmaxf(((float)h + 0.5f) * (1.0f/TH) - 0.5f, 0.0f), 7.0f);
    int   y0 = min((int)cy, GRIDN - 2);
    float wy = cy - (float)y0;

    const float* lutn = g_tilelut + (size_t)n * NTILES * NBINS;
    const float* eqn  = g_eqlut + n * NBINS;

    float4 R0, G0, Bl0, R1, G1, Bl1;
    #pragma unroll
    for (int k = 0; k < 4; k++) {
        int w = w0 + k;
        int v = (k==0)?v4.x:(k==1)?v4.y:(k==2)?v4.z:v4.w;
        float a = (k==0)?A4.x:(k==1)?A4.y:(k==2)?A4.z:A4.w;
        float b = (k==0)?B4.x:(k==1)?B4.y:(k==2)?B4.z:B4.w;

        float eq_l = eqn[v];

        float cx = fminf(fmaxf(((float)w + 0.5f) * (1.0f/TW) - 0.5f, 0.0f), 7.0f);
        int   x0 = min((int)cx, GRIDN - 2);
        float wx = cx - (float)x0;
        const float* p00 = lutn + ((y0 * GRIDN + x0) * NBINS + v);
        float v00 = p00[0];
        float v01 = p00[NBINS];
        float v10 = p00[GRIDN * NBINS];
        float v11 = p00[GRIDN * NBINS + NBINS];
        float top = v00 + (v01 - v00) * wx;
        float bot = v10 + (v11 - v10) * wx;
        float cl_l = top + (bot - top) * wy;

        float r0, g0, b0, r1, g1, b1;
        lab2rgb255(eq_l, a, b, r0, g0, b0);
        lab2rgb255(cl_l, a, b, r1, g1, b1);
        if (k==0){R0.x=r0;G0.x=g0;Bl0.x=b0;R1.x=r1;G1.x=g1;Bl1.x=b1;}
        else if (k==1){R0.y=r0;G0.y=g0;Bl0.y=b0;R1.y=r1;G1.y=g1;Bl1.y=b1;}
        else if (k==2){R0.z=r0;G0.z=g0;Bl0.z=b0;R1.z=r1;G1.z=g1;Bl1.z=b1;}
        else {R0.w=r0;G0.w=g0;Bl0.w=b0;R1.w=r1;G1.w=g1;Bl1.w=b1;}
    }

    size_t base0 = (size_t)n * 3 * HW + hw;        // equalize output
    size_t base1 = (size_t)NPIX * 3 + base0;       // clahe output
    *(float4*)(out + base0)          = R0;
    *(float4*)(out + base0 + HW)     = G0;
    *(float4*)(out + base0 + 2*HW)   = Bl0;
    *(float4*)(out + base1)          = R1;
    *(float4*)(out + base1 + HW)     = G1;
    *(float4*)(out + base1 + 2*HW)   = Bl1;
}

// ---------------- launch ----------------
extern "C" void kernel_launch(void* const* d_in, const int* in_sizes, int n_in,
                              void* d_out, int out_size) {
    const float* x = (const float*)d_in[0];
    float* out = (float*)d_out;
    (void)in_sizes; (void)n_in; (void)out_size;

    k_init<<<1, 32>>>();
    k_lab<<<NPIX / 4 / 256, 256>>>(x);
    k_quant_hist<<<N_IMG * NTILES, 256>>>();
    k_luts<<<N_IMG * NTILES + N_IMG, NBINS>>>();
    k_out<<<NPIX / 4 / 256, 256>>>(out);
}

// round 3
// speedup vs baseline: 2.6529x; 1.3776x over previous
#include <cuda_runtime.h>
#include <cuda_fp16.h>
#include <math.h>

#define N_IMG 16
#define HH 512
#define WW 512
#define HW (HH*WW)
#define NPIX (N_IMG*HW)
#define GRIDN 8
#define TH 64
#define TW 64
#define AREA (TH*TW)
#define NBINS 256
#define NTILES (GRIDN*GRIDN)
#define LAB_BLOCKS (NPIX/4/256)          // 4096
#define BLK_PER_IMG (LAB_BLOCKS/N_IMG)   // 256

#define LAB_EPS (216.0f/24389.0f)
#define LAB_KAPPA (24389.0f/27.0f)

// ---------------- scratch (no allocations allowed) ----------------
__device__ float   g_L[NPIX];
__device__ __half2 g_ab[NPIX];
__device__ unsigned char g_lint[NPIX];
__device__ float g_blkmin[LAB_BLOCKS];
__device__ float g_blkmax[LAB_BLOCKS];
__device__ int   g_tilehist[N_IMG*NTILES*NBINS];
__device__ float g_tilelut [N_IMG*NTILES*NBINS];
__device__ float g_eqlut   [N_IMG*NBINS];

// ---------------- helpers ----------------
__device__ __forceinline__ float srgb2lin(float c) {
    return (c <= 0.04045f) ? (c * (1.0f/12.92f))
                           : __powf((c + 0.055f) * (1.0f/1.055f), 2.4f);
}
__device__ __forceinline__ float labf(float x) {
    return (x > LAB_EPS) ? cbrtf(x) : (LAB_KAPPA * x + 16.0f) * (1.0f/116.0f);
}
__device__ __forceinline__ float lin2srgb_fast(float c) {
    c = fmaxf(c, 0.0f);
    return (c <= 0.0031308f) ? (c * 12.92f)
                             : (1.055f * __powf(c, 1.0f/2.4f) - 0.055f);
}
__device__ __forceinline__ float labfinv(float f) {
    float f3 = f * f * f;
    return (f3 > LAB_EPS) ? f3 : (116.0f * f - 16.0f) * (1.0f/LAB_KAPPA);
}
__device__ __forceinline__ float clamp01(float c) {
    return fminf(fmaxf(c, 0.0f), 1.0f);
}

__device__ __forceinline__ void lab2rgb255(float l255, float a, float b,
                                           float& r, float& g, float& bl) {
    float L  = l255 * (100.0f / 255.0f);
    float fy = (L + 16.0f) * (1.0f/116.0f);
    float fx = fy + a * (1.0f/500.0f);
    float fz = fy - b * (1.0f/200.0f);
    float X = labfinv(fx) * 0.95047f;
    float Y = labfinv(fy);
    float Z = labfinv(fz) * 1.08883f;
    float rl =  3.2404542f*X - 1.5371385f*Y - 0.4985314f*Z;
    float gl = -0.9692660f*X + 1.8760108f*Y + 0.0415560f*Z;
    float bb =  0.0556434f*X - 0.2040259f*Y + 1.0572252f*Z;
    r  = 255.0f * clamp01(lin2srgb_fast(rl));
    g  = 255.0f * clamp01(lin2srgb_fast(gl));
    bl = 255.0f * clamp01(lin2srgb_fast(bb));
}

__device__ __forceinline__ float inclusive_scan_256(float v, float* ws8) {
    int lane = threadIdx.x & 31, warp = threadIdx.x >> 5;
    #pragma unroll
    for (int o = 1; o < 32; o <<= 1) {
        float t = __shfl_up_sync(0xFFFFFFFFu, v, o);
        if (lane >= o) v += t;
    }
    if (lane == 31) ws8[warp] = v;
    __syncthreads();
    if (warp == 0 && lane < 8) {
        float s = ws8[lane];
        #pragma unroll
        for (int o = 1; o < 8; o <<= 1) {
            float t = __shfl_up_sync(0xFFu, s, o);
            if (lane >= o) s += t;
        }
        ws8[lane] = s;
    }
    __syncthreads();
    if (warp > 0) v += ws8[warp - 1];
    return v;
}

// ---------------- K1: RGB -> Lab + per-block min/max of L ----------------
__global__ void k_lab(const float* __restrict__ x) {
    int t  = blockIdx.x * blockDim.x + threadIdx.x;
    int p4 = t * 4;
    int n  = blockIdx.x / BLK_PER_IMG;
    int hw = p4 - n * HW;
    const float* img = x + (size_t)n * 3 * HW;
    float4 R = *(const float4*)(img + hw);
    float4 G = *(const float4*)(img + HW + hw);
    float4 B = *(const float4*)(img + 2*HW + hw);

    float4 Lo;
    __half2 ab[4];
    float vmin =  1e30f, vmax = -1e30f;
    #pragma unroll
    for (int k = 0; k < 4; k++) {
        float r = (k==0)?R.x:(k==1)?R.y:(k==2)?R.z:R.w;
        float g = (k==0)?G.x:(k==1)?G.y:(k==2)?G.z:G.w;
        float b = (k==0)?B.x:(k==1)?B.y:(k==2)?B.z:B.w;
        float lr = srgb2lin(r), lg = srgb2lin(g), lb = srgb2lin(b);
        float X = (0.4124564f*lr + 0.3575761f*lg + 0.1804375f*lb) * (1.0f/0.95047f);
        float Y = (0.2126729f*lr + 0.7151522f*lg + 0.0721750f*lb);
        float Z = (0.0193339f*lr + 0.1191920f*lg + 0.9503041f*lb) * (1.0f/1.08883f);
        float fx = labf(X), fy = labf(Y), fz = labf(Z);
        float L = 116.0f * fy - 16.0f;
        ab[k] = __floats2half2_rn(500.0f * (fx - fy), 200.0f * (fy - fz));
        if (k==0) Lo.x=L; else if(k==1) Lo.y=L; else if (k==2) Lo.z=L; else Lo.w=L;
        vmin = fminf(vmin, L); vmax = fmaxf(vmax, L);
    }
    *(float4*)(g_L + p4) = Lo;
    *(uint2*)(g_ab + p4) = *(uint2*)ab;
    *(uint2*)(g_ab + p4 + 2) = *(uint2*)(ab + 2);

    #pragma unroll
    for (int o = 16; o > 0; o >>= 1) {
        vmin = fminf(vmin, __shfl_down_sync(0xFFFFFFFFu, vmin, o));
        vmax = fmaxf(vmax, __shfl_down_sync(0xFFFFFFFFu, vmax, o));
    }
    __shared__ float wmin[8], wmax[8];
    int lane = threadIdx.x & 31, warp = threadIdx.x >> 5;
    if (lane == 0) { wmin[warp] = vmin; wmax[warp] = vmax; }
    __syncthreads();
    if (threadIdx.x == 0) {
        float bmin = wmin[0], bmax = wmax[0];
        #pragma unroll
        for (int i = 1; i < 8; i++) {
            bmin = fminf(bmin, wmin[i]);
            bmax = fmaxf(bmax, wmax[i]);
        }
        g_blkmin[blockIdx.x] = bmin;
        g_blkmax[blockIdx.x] = bmax;
    }
}

// ---------------- K2: finalize min/max + quantize + per-tile histograms ----------------
// one block per tile: blockIdx = n*64 + tile, 256 threads
__global__ void k_quant_hist() {
    int blk = blockIdx.x;
    int n = blk >> 6;
    int t = blk & 63;
    int ty = t >> 3, tx = t & 7;

    __shared__ int sh[NBINS];
    __shared__ float wmin[8], wmax[8];
    __shared__ float s_lmin, s_scale;

    // reduce this image's 256 per-block min/max (one value per thread)
    float vmin = g_blkmin[n * BLK_PER_IMG + threadIdx.x];
    float vmax = g_blkmax[n * BLK_PER_IMG + threadIdx.x];
    #pragma unroll
    for (int o = 16; o > 0; o >>= 1) {
        vmin = fminf(vmin, __shfl_down_sync(0xFFFFFFFFu, vmin, o));
        vmax = fmaxf(vmax, __shfl_down_sync(0xFFFFFFFFu, vmax, o));
    }
    int lane = threadIdx.x & 31, warp = threadIdx.x >> 5;
    if (lane == 0) { wmin[warp] = vmin; wmax[warp] = vmax; }
    sh[threadIdx.x] = 0;
    __syncthreads();
    if (threadIdx.x == 0) {
        float bmin = wmin[0], bmax = wmax[0];
        #pragma unroll
        for (int i = 1; i < 8; i++) {
            bmin = fminf(bmin, wmin[i]);
            bmax = fmaxf(bmax, wmax[i]);
        }
        s_lmin = bmin;
        s_scale = 255.0f / (bmax - bmin + 1e-6f);
    }
    __syncthreads();

    float lmin = s_lmin, scale = s_scale;
    int base = n * HW + (ty * TH) * WW + tx * TW;
    #pragma unroll
    for (int it = 0; it < 4; it++) {
        int i = threadIdx.x + it * 256;          // 0..1023 float4 chunks
        int row = i >> 4, c16 = i & 15;
        int p = base + row * WW + c16 * 4;
        float4 L4 = *(const float4*)(g_L + p);
        int v0 = min(max((int)rintf((L4.x - lmin) * scale), 0), 255);
        int v1 = min(max((int)rintf((L4.y - lmin) * scale), 0), 255);
        int v2 = min(max((int)rintf((L4.z - lmin) * scale), 0), 255);
        int v3 = min(max((int)rintf((L4.w - lmin) * scale), 0), 255);
        *(uchar4*)(g_lint + p) = make_uchar4((unsigned char)v0, (unsigned char)v1,
                                             (unsigned char)v2, (unsigned char)v3);
        atomicAdd(&sh[v0], 1);
        atomicAdd(&sh[v1], 1);
        atomicAdd(&sh[v2], 1);
        atomicAdd(&sh[v3], 1);
    }
    __syncthreads();
    g_tilehist[blk * NBINS + threadIdx.x] = sh[threadIdx.x];
}

// ---------------- K3: both LUT families ----------------
__global__ void k_luts() {
    __shared__ float ws8[8];
    __shared__ float totc;
    int blk = blockIdx.x;
    int t = threadIdx.x;
    if (blk < N_IMG * NTILES) {
        float hv = (float)g_tilehist[blk * NBINS + t];
        float clipped = fminf(hv, 32.0f);       // max(2.0*4096/256, 1.0)
        float cum = inclusive_scan_256(clipped, ws8);
        if (t == 255) totc = cum;
        __syncthreads();
        float excess = (float)AREA - totc;      // hist sums to exactly AREA
        float val = cum + (float)(t + 1) * (excess * (1.0f/256.0f));
        g_tilelut[blk * NBINS + t] = rintf(val * (255.0f / (float)AREA));
    } else {
        int n = blk - N_IMG * NTILES;
        int s = 0;
        #pragma unroll
        for (int tt = 0; tt < NTILES; tt++)
            s += g_tilehist[(n * NTILES + tt) * NBINS + t];
        float cum = inclusive_scan_256((float)s, ws8);
        g_eqlut[n * NBINS + t] = rintf(cum * (255.0f / (float)HW));
    }
}

// ---------------- K4: reconstruct both outputs (4 px/thread) ----------------
__global__ void k_out(float* __restrict__ out) {
    int t  = blockIdx.x * blockDim.x + threadIdx.x;
    int p4 = t * 4;
    int n  = blockIdx.x / BLK_PER_IMG;
    int hw = p4 - n * HW;
    int h = hw >> 9, w0 = hw & 511;

    uchar4 v4 = *(const uchar4*)(g_lint + p4);
    uint4 abraw = *(const uint4*)(g_ab + p4);

    float cy = fminf(fmaxf(((float)h + 0.5f) * (1.0f/TH) - 0.5f, 0.0f), 7.0f);
    int   y0 = min((int)cy, GRIDN - 2);
    float wy = cy - (float)y0;

    const float* lutn = g_tilelut + (size_t)n * NTILES * NBINS;
    const float* eqn  = g_eqlut + n * NBINS;

    float4 R0, G0, Bl0, R1, G1, Bl1;
    #pragma unroll
    for (int k = 0; k < 4; k++) {
        int w = w0 + k;
        int v = (k==0)?v4.x:(k==1)?v4.y:(k==2)?v4.z:v4.w;
        unsigned int abu = (k==0)?abraw.x:(k==1)?abraw.y:(k==2)?abraw.z:abraw.w;
        float2 abf = __half22float2(*(__half2*)&abu);
        float a = abf.x, b = abf.y;

        float eq_l = eqn[v];

        float cx = fminf(fmaxf(((float)w + 0.5f) * (1.0f/TW) - 0.5f, 0.0f), 7.0f);
        int   x0 = min((int)cx, GRIDN - 2);
        float wx = cx - (float)x0;
        const float* p00 = lutn + ((y0 * GRIDN + x0) * NBINS + v);
        float v00 = p00[0];
        float v01 = p00[NBINS];
        float v10 = p00[GRIDN * NBINS];
        float v11 = p00[GRIDN * NBINS + NBINS];
        float top = v00 + (v01 - v00) * wx;
        float bot = v10 + (v11 - v10) * wx;
        float cl_l = top + (bot - top) * wy;

        float r0, g0, b0, r1, g1, b1;
        lab2rgb255(eq_l, a, b, r0, g0, b0);
        lab2rgb255(cl_l, a, b, r1, g1, b1);
        if (k==0){R0.x=r0;G0.x=g0;Bl0.x=b0;R1.x=r1;G1.x=g1;Bl1.x=b1;}
        else if (k==1){R0.y=r0;G0.y=g0;Bl0.y=b0;R1.y=r1;G1.y=g1;Bl1.y=b1;}
        else if (k==2){R0.z=r0;G0.z=g0;Bl0.z=b0;R1.z=r1;G1.z=g1;Bl1.z=b1;}
        else {R0.w=r0;G0.w=g0;Bl0.w=b0;R1.w=r1;G1.w=g1;Bl1.w=b1;}
    }

    size_t base0 = (size_t)n * 3 * HW + hw;        // equalize output
    size_t base1 = (size_t)NPIX * 3 + base0;       // clahe output
    *(float4*)(out + base0)          = R0;
    *(float4*)(out + base0 + HW)     = G0;
    *(float4*)(out + base0 + 2*HW)   = Bl0;
    *(float4*)(out + base1)          = R1;
    *(float4*)(out + base1 + HW)     = G1;
    *(float4*)(out + base1 + 2*HW)   = Bl1;
}

// ---------------- launch ----------------
extern "C" void kernel_launch(void* const* d_in, const int* in_sizes, int n_in,
                              void* d_out, int out_size) {
    const float* x = (const float*)d_in[0];
    float* out = (float*)d_out;
    (void)in_sizes; (void)n_in; (void)out_size;

    k_lab<<<LAB_BLOCKS, 256>>>(x);
    k_quant_hist<<<N_IMG * NTILES, 256>>>();
    k_luts<<<N_IMG * NTILES + N_IMG, NBINS>>>();
    k_out<<<LAB_BLOCKS, 256>>>(out);
}

// round 4
// speedup vs baseline: 2.8423x; 1.0714x over previous
#include <cuda_runtime.h>
#include <cuda_fp16.h>
#include <math.h>

#define N_IMG 16
#define HH 512
#define WW 512
#define HW (HH*WW)
#define NPIX (N_IMG*HW)
#define GRIDN 8
#define TH 64
#define TW 64
#define AREA (TH*TW)
#define NBINS 256
#define NTILES (GRIDN*GRIDN)
#define LAB_BLOCKS (NPIX/4/256)          // 4096
#define BLK_PER_IMG (LAB_BLOCKS/N_IMG)   // 256

#define LAB_EPS (216.0f/24389.0f)
#define LAB_KAPPA (24389.0f/27.0f)

// ---------------- scratch (no allocations allowed) ----------------
__device__ float   g_L[NPIX];
__device__ __half2 g_ab[NPIX];
__device__ unsigned char g_lint[NPIX];
__device__ float g_blkmin[LAB_BLOCKS];
__device__ float g_blkmax[LAB_BLOCKS];
__device__ int   g_tilehist[N_IMG*NTILES*NBINS];
__device__ float g_tilelut [N_IMG*NTILES*NBINS];
__device__ float g_eqlut   [N_IMG*NBINS];

// ---------------- MUFU primitives ----------------
__device__ __forceinline__ float ex2f(float x){ float r; asm("ex2.approx.f32 %0, %1;" : "=f"(r) : "f"(x)); return r; }
__device__ __forceinline__ float lg2f(float x){ float r; asm("lg2.approx.f32 %0, %1;" : "=f"(r) : "f"(x)); return r; }

// ---------------- helpers ----------------
__device__ __forceinline__ float srgb2lin(float c) {
    // ((c+0.055)/1.055)^2.4 for c>0.04045 else c/12.92
    float lin = c * (1.0f/12.92f);
    float p = ex2f(2.4f * lg2f((c + 0.055f) * (1.0f/1.055f)));
    return (c <= 0.04045f) ? lin : p;
}
__device__ __forceinline__ float labf(float x) {
    // cbrt(x) for x>EPS else (kappa*x+16)/116
    float lin = fmaf(x, LAB_KAPPA/116.0f, 16.0f/116.0f);
    float p = ex2f(lg2f(x) * (1.0f/3.0f));
    return (x > LAB_EPS) ? p : lin;
}
__device__ __forceinline__ float finv(float f) {
    float f3 = f * f * f;
    float lin = fmaf(f, 116.0f/LAB_KAPPA, -16.0f/LAB_KAPPA);
    return (f3 > LAB_EPS) ? f3 : lin;
}
// 255 * clip(lin2srgb(c), 0, 1), fused constants
__device__ __forceinline__ float srgb255(float c) {
    float lin = c * (12.92f * 255.0f);
    // 255*1.055*c^(1/2.4) - 255*0.055 ; log2(269.025)=8.0715942
    float p = ex2f(fmaf(lg2f(c), 1.0f/2.4f, 8.0715942f)) - 14.025f;
    float r = (c <= 0.0031308f) ? lin : p;   // covers c<=0 too (lin<0 -> clamp)
    return fminf(fmaxf(r, 0.0f), 255.0f);
}

// dual Lab->RGB255 with shared a,b ; WP folded into matrix
__device__ __forceinline__ void lab2rgb255_dual(
    float eq_l, float cl_l, float a, float b,
    float& r0, float& g0, float& b0, float& r1, float& g1, float& b1)
{
    float a500 = a * (1.0f/500.0f);
    float b200 = b * (1.0f/200.0f);
    float fy0 = fmaf(eq_l, 100.0f/(255.0f*116.0f), 16.0f/116.0f);
    float fy1 = fmaf(cl_l, 100.0f/(255.0f*116.0f), 16.0f/116.0f);
    float fx0 = fy0 + a500, fx1 = fy1 + a500;
    float fz0 = fy0 - b200, fz1 = fy1 - b200;
    float X0 = finv(fx0), Y0 = finv(fy0), Z0 = finv(fz0);
    float X1 = finv(fx1), Y1 = finv(fy1), Z1 = finv(fz1);
    // matrix with WP folded: M[i][j] * wp[j]
    #define MRL(X,Y,Z) ( 3.0799546f*(X) - 1.5371385f*(Y) - 0.5428164f*(Z))
    #define MGL(X,Y,Z) (-0.9212582f*(X) + 1.8760108f*(Y) + 0.0452474f*(Z))
    #define MBL(X,Y,Z) ( 0.0528874f*(X) - 0.2040259f*(Y) + 1.1511382f*(Z))
    r0 = srgb255(MRL(X0,Y0,Z0));
    g0 = srgb255(MGL(X0,Y0,Z0));
    b0 = srgb255(MBL(X0,Y0,Z0));
    r1 = srgb255(MRL(X1,Y1,Z1));
    g1 = srgb255(MGL(X1,Y1,Z1));
    b1 = srgb255(MBL(X1,Y1,Z1));
    #undef MRL
    #undef MGL
    #undef MBL
}

__device__ __forceinline__ float inclusive_scan_256(float v, float* ws8) {
    int lane = threadIdx.x & 31, warp = threadIdx.x >> 5;
    #pragma unroll
    for (int o = 1; o < 32; o <<= 1) {
        float t = __shfl_up_sync(0xFFFFFFFFu, v, o);
        if (lane >= o) v += t;
    }
    if (lane == 31) ws8[warp] = v;
    __syncthreads();
    if (warp == 0 && lane < 8) {
        float s = ws8[lane];
        #pragma unroll
        for (int o = 1; o < 8; o <<= 1) {
            float t = __shfl_up_sync(0xFFu, s, o);
            if (lane >= o) s += t;
        }
        ws8[lane] = s;
    }
    __syncthreads();
    if (warp > 0) v += ws8[warp - 1];
    return v;
}

// ---------------- K1: RGB -> Lab + per-block min/max of L ----------------
__global__ void k_lab(const float* __restrict__ x) {
    int t  = blockIdx.x * blockDim.x + threadIdx.x;
    int p4 = t * 4;
    int n  = blockIdx.x / BLK_PER_IMG;
    int hw = p4 - n * HW;
    const float* img = x + (size_t)n * 3 * HW;
    float4 R = *(const float4*)(img + hw);
    float4 G = *(const float4*)(img + HW + hw);
    float4 B = *(const float4*)(img + 2*HW + hw);

    float4 Lo;
    __half2 ab[4];
    float vmin =  1e30f, vmax = -1e30f;
    #pragma unroll
    for (int k = 0; k < 4; k++) {
        float r = (k==0)?R.x:(k==1)?R.y:(k==2)?R.z:R.w;
        float g = (k==0)?G.x:(k==1)?G.y:(k==2)?G.z:G.w;
        float b = (k==0)?B.x:(k==1)?B.y:(k==2)?B.z:B.w;
        float lr = srgb2lin(r), lg = srgb2lin(g), lb = srgb2lin(b);
        // RGB->XYZ with 1/WP folded into coefficients
        float X = 0.43395038f*lr + 0.37621015f*lg + 0.18984050f*lb;
        float Y = 0.21267290f*lr + 0.71515220f*lg + 0.07217500f*lb;
        float Z = 0.01775650f*lr + 0.10946790f*lg + 0.87277544f*lb;
        float fx = labf(X), fy = labf(Y), fz = labf(Z);
        float L = 116.0f * fy - 16.0f;
        ab[k] = __floats2half2_rn(500.0f * (fx - fy), 200.0f * (fy - fz));
        if (k==0) Lo.x=L; else if(k==1) Lo.y=L; else if (k==2) Lo.z=L; else Lo.w=L;
        vmin = fminf(vmin, L); vmax = fmaxf(vmax, L);
    }
    *(float4*)(g_L + p4) = Lo;
    *(uint2*)(g_ab + p4) = *(uint2*)ab;
    *(uint2*)(g_ab + p4 + 2) = *(uint2*)(ab + 2);

    #pragma unroll
    for (int o = 16; o > 0; o >>= 1) {
        vmin = fminf(vmin, __shfl_down_sync(0xFFFFFFFFu, vmin, o));
        vmax = fmaxf(vmax, __shfl_down_sync(0xFFFFFFFFu, vmax, o));
    }
    __shared__ float wmin[8], wmax[8];
    int lane = threadIdx.x & 31, warp = threadIdx.x >> 5;
    if (lane == 0) { wmin[warp] = vmin; wmax[warp] = vmax; }
    __syncthreads();
    if (threadIdx.x == 0) {
        float bmin = wmin[0], bmax = wmax[0];
        #pragma unroll
        for (int i = 1; i < 8; i++) {
            bmin = fminf(bmin, wmin[i]);
            bmax = fmaxf(bmax, wmax[i]);
        }
        g_blkmin[blockIdx.x] = bmin;
        g_blkmax[blockIdx.x] = bmax;
    }
}

// ---------------- K2: min/max finalize + quantize + tile hist + tile LUT ----------------
// one block per tile: blockIdx = n*64 + tile, 256 threads
__global__ void k_quant_hist_lut() {
    int blk = blockIdx.x;
    int n = blk >> 6;
    int t = blk & 63;
    int ty = t >> 3, tx = t & 7;

    __shared__ int sh[NBINS];
    __shared__ float wmin[8], wmax[8];
    __shared__ float ws8[8];
    __shared__ float s_lmin, s_scale;

    // reduce this image's 256 per-block min/max (one value per thread)
    float vmin = g_blkmin[n * BLK_PER_IMG + threadIdx.x];
    float vmax = g_blkmax[n * BLK_PER_IMG + threadIdx.x];
    #pragma unroll
    for (int o = 16; o > 0; o >>= 1) {
        vmin = fminf(vmin, __shfl_down_sync(0xFFFFFFFFu, vmin, o));
        vmax = fmaxf(vmax, __shfl_down_sync(0xFFFFFFFFu, vmax, o));
    }
    int lane = threadIdx.x & 31, warp = threadIdx.x >> 5;
    if (lane == 0) { wmin[warp] = vmin; wmax[warp] = vmax; }
    sh[threadIdx.x] = 0;
    __syncthreads();
    if (threadIdx.x == 0) {
        float bmin = wmin[0], bmax = wmax[0];
        #pragma unroll
        for (int i = 1; i < 8; i++) {
            bmin = fminf(bmin, wmin[i]);
            bmax = fmaxf(bmax, wmax[i]);
        }
        s_lmin = bmin;
        s_scale = 255.0f / (bmax - bmin + 1e-6f);
    }
    __syncthreads();

    float lmin = s_lmin, scale = s_scale;
    int base = n * HW + (ty * TH) * WW + tx * TW;
    #pragma unroll
    for (int it = 0; it < 4; it++) {
        int i = threadIdx.x + it * 256;          // 0..1023 float4 chunks
        int row = i >> 4, c16 = i & 15;
        int p = base + row * WW + c16 * 4;
        float4 L4 = *(const float4*)(g_L + p);
        int v0 = min(max((int)rintf((L4.x - lmin) * scale), 0), 255);
        int v1 = min(max((int)rintf((L4.y - lmin) * scale), 0), 255);
        int v2 = min(max((int)rintf((L4.z - lmin) * scale), 0), 255);
        int v3 = min(max((int)rintf((L4.w - lmin) * scale), 0), 255);
        *(uchar4*)(g_lint + p) = make_uchar4((unsigned char)v0, (unsigned char)v1,
                                             (unsigned char)v2, (unsigned char)v3);
        atomicAdd(&sh[v0], 1);
        atomicAdd(&sh[v1], 1);
        atomicAdd(&sh[v2], 1);
        atomicAdd(&sh[v3], 1);
    }
    __syncthreads();

    int hist = sh[threadIdx.x];
    g_tilehist[blk * NBINS + threadIdx.x] = hist;

    // CLAHE LUT for this tile, built in-place
    float clipped = fminf((float)hist, 32.0f);   // max(2.0*4096/256, 1.0)
    float cum = inclusive_scan_256(clipped, ws8);
    float totc = __shfl_sync(0xFFFFFFFFu, cum, 31);   // only valid in last warp
    __shared__ float s_totc;
    if (threadIdx.x == 255) s_totc = cum;
    __syncthreads();
    float excess = (float)AREA - s_totc;          // hist sums to exactly AREA
    (void)totc;
    float val = cum + (float)(threadIdx.x + 1) * (excess * (1.0f/256.0f));
    g_tilelut[blk * NBINS + threadIdx.x] = rintf(val * (255.0f / (float)AREA));
}

// ---------------- K3: equalize LUT per image ----------------
__global__ void k_eqlut() {
    __shared__ float ws8[8];
    int n = blockIdx.x;
    int t = threadIdx.x;
    int s = 0;
    #pragma unroll
    for (int tt = 0; tt < NTILES; tt++)
        s += g_tilehist[(n * NTILES + tt) * NBINS + t];
    float cum = inclusive_scan_256((float)s, ws8);
    g_eqlut[n * NBINS + t] = rintf(cum * (255.0f / (float)HW));
}

// ---------------- K4: reconstruct both outputs (4 px/thread) ----------------
__global__ void k_out(float* __restrict__ out) {
    int t  = blockIdx.x * blockDim.x + threadIdx.x;
    int p4 = t * 4;
    int n  = blockIdx.x / BLK_PER_IMG;
    int hw = p4 - n * HW;
    int h = hw >> 9, w0 = hw & 511;

    uchar4 v4 = *(const uchar4*)(g_lint + p4);
    uint4 abraw = *(const uint4*)(g_ab + p4);

    float cy = fminf(fmaxf(((float)h + 0.5f) * (1.0f/TH) - 0.5f, 0.0f), 7.0f);
    int   y0 = min((int)cy, GRIDN - 2);
    float wy = cy - (float)y0;

    const float* lutn = g_tilelut + (size_t)n * NTILES * NBINS;
    const float* eqn  = g_eqlut + n * NBINS;

    float4 R0, G0, Bl0, R1, G1, Bl1;
    #pragma unroll
    for (int k = 0; k < 4; k++) {
        int w = w0 + k;
        int v = (k==0)?v4.x:(k==1)?v4.y:(k==2)?v4.z:v4.w;
        unsigned int abu = (k==0)?abraw.x:(k==1)?abraw.y:(k==2)?abraw.z:abraw.w;
        float2 abf = __half22float2(*(__half2*)&abu);

        float eq_l = eqn[v];

        float cx = fminf(fmaxf(((float)w + 0.5f) * (1.0f/TW) - 0.5f, 0.0f), 7.0f);
        int   x0 = min((int)cx, GRIDN - 2);
        float wx = cx - (float)x0;
        const float* p00 = lutn + ((y0 * GRIDN + x0) * NBINS + v);
        float v00 = p00[0];
        float v01 = p00[NBINS];
        float v10 = p00[GRIDN * NBINS];
        float v11 = p00[GRIDN * NBINS + NBINS];
        float top = v00 + (v01 - v00) * wx;
        float bot = v10 + (v11 - v10) * wx;
        float cl_l = top + (bot - top) * wy;

        float r0, g0, b0, r1, g1, b1;
        lab2rgb255_dual(eq_l, cl_l, abf.x, abf.y, r0, g0, b0, r1, g1, b1);
        if (k==0){R0.x=r0;G0.x=g0;Bl0.x=b0;R1.x=r1;G1.x=g1;Bl1.x=b1;}
        else if (k==1){R0.y=r0;G0.y=g0;Bl0.y=b0;R1.y=r1;G1.y=g1;Bl1.y=b1;}
        else if (k==2){R0.z=r0;G0.z=g0;Bl0.z=b0;R1.z=r1;G1.z=g1;Bl1.z=b1;}
        else {R0.w=r0;G0.w=g0;Bl0.w=b0;R1.w=r1;G1.w=g1;Bl1.w=b1;}
    }

    size_t base0 = (size_t)n * 3 * HW + hw;        // equalize output
    size_t base1 = (size_t)NPIX * 3 + base0;       // clahe output
    *(float4*)(out + base0)          = R0;
    *(float4*)(out + base0 + HW)     = G0;
    *(float4*)(out + base0 + 2*HW)   = Bl0;
    *(float4*)(out + base1)          = R1;
    *(float4*)(out + base1 + HW)     = G1;
    *(float4*)(out + base1 + 2*HW)   = Bl1;
}

// ---------------- launch ----------------
extern "C" void kernel_launch(void* const* d_in, const int* in_sizes, int n_in,
                              void* d_out, int out_size) {
    const float* x = (const float*)d_in[0];
    float* out = (float*)d_out;
    (void)in_sizes; (void)n_in; (void)out_size;

    k_lab<<<LAB_BLOCKS, 256>>>(x);
    k_quant_hist_lut<<<N_IMG * NTILES, 256>>>();
    k_eqlut<<<N_IMG, NBINS>>>();
    k_out<<<LAB_BLOCKS, 256>>>(out);
}

// round 5
// speedup vs baseline: 2.9298x; 1.0308x over previous
#include <cuda_runtime.h>
#include <cuda_fp16.h>
#include <math.h>

#define N_IMG 16
#define HH 512
#define WW 512
#define HW (HH*WW)
#define NPIX (N_IMG*HW)
#define GRIDN 8
#define TH 64
#define TW 64
#define AREA (TH*TW)
#define NBINS 256
#define NTILES (GRIDN*GRIDN)
#define LAB_BLOCKS (NPIX/4/256)          // 4096
#define BLK_PER_IMG (LAB_BLOCKS/N_IMG)   // 256

#define LAB_EPS (216.0f/24389.0f)
#define LAB_KAPPA (24389.0f/27.0f)

// ---------------- scratch (no allocations allowed) ----------------
__device__ float   g_L[NPIX];
__device__ __half2 g_ab[NPIX];
__device__ unsigned char g_lint[NPIX];
__device__ float g_blkmin[LAB_BLOCKS];
__device__ float g_blkmax[LAB_BLOCKS];
__device__ int    g_tilehist[N_IMG*NTILES*NBINS];
__device__ float  g_tilelut [N_IMG*NTILES*NBINS];
__device__ float2 g_eqlut2  [N_IMG*NBINS];   // (fy0, finv(fy0)) per bin

// ---------------- MUFU primitives ----------------
__device__ __forceinline__ float ex2f(float x){ float r; asm("ex2.approx.f32 %0, %1;" : "=f"(r) : "f"(x)); return r; }
__device__ __forceinline__ float lg2f(float x){ float r; asm("lg2.approx.f32 %0, %1;" : "=f"(r) : "f"(x)); return r; }

// ---------------- helpers ----------------
__device__ __forceinline__ float srgb2lin(float c) {
    float lin = c * (1.0f/12.92f);
    float p = ex2f(2.4f * lg2f((c + 0.055f) * (1.0f/1.055f)));
    return (c <= 0.04045f) ? lin : p;
}
__device__ __forceinline__ float labf(float x) {
    float lin = fmaf(x, LAB_KAPPA/116.0f, 16.0f/116.0f);
    float p = ex2f(lg2f(x) * (1.0f/3.0f));
    return (x > LAB_EPS) ? p : lin;
}
__device__ __forceinline__ float finv(float f) {
    float f3 = f * f * f;
    float lin = fmaf(f, 116.0f/LAB_KAPPA, -16.0f/LAB_KAPPA);
    return (f3 > LAB_EPS) ? f3 : lin;
}
// 255 * clip(lin2srgb(c), 0, 1), fused constants
__device__ __forceinline__ float srgb255(float c) {
    float lin = c * (12.92f * 255.0f);
    float p = ex2f(fmaf(lg2f(c), 1.0f/2.4f, 8.0715942f)) - 14.025f;  // log2(255*1.055)
    float r = (c <= 0.0031308f) ? lin : p;
    return fminf(fmaxf(r, 0.0f), 255.0f);
}

__device__ __forceinline__ float inclusive_scan_256(float v, float* ws8) {
    int lane = threadIdx.x & 31, warp = threadIdx.x >> 5;
    #pragma unroll
    for (int o = 1; o < 32; o <<= 1) {
        float t = __shfl_up_sync(0xFFFFFFFFu, v, o);
        if (lane >= o) v += t;
    }
    if (lane == 31) ws8[warp] = v;
    __syncthreads();
    if (warp == 0 && lane < 8) {
        float s = ws8[lane];
        #pragma unroll
        for (int o = 1; o < 8; o <<= 1) {
            float t = __shfl_up_sync(0xFFu, s, o);
            if (lane >= o) s += t;
        }
        ws8[lane] = s;
    }
    __syncthreads();
    if (warp > 0) v += ws8[warp - 1];
    return v;
}

// ---------------- K1: RGB -> Lab + per-block min/max of L ----------------
__global__ void k_lab(const float* __restrict__ x) {
    int t  = blockIdx.x * blockDim.x + threadIdx.x;
    int p4 = t * 4;
    int n  = blockIdx.x / BLK_PER_IMG;
    int hw = p4 - n * HW;
    const float* img = x + (size_t)n * 3 * HW;
    float4 R = *(const float4*)(img + hw);
    float4 G = *(const float4*)(img + HW + hw);
    float4 B = *(const float4*)(img + 2*HW + hw);

    float4 Lo;
    __half2 ab[4];
    float vmin =  1e30f, vmax = -1e30f;
    #pragma unroll
    for (int k = 0; k < 4; k++) {
        float r = (k==0)?R.x:(k==1)?R.y:(k==2)?R.z:R.w;
        float g = (k==0)?G.x:(k==1)?G.y:(k==2)?G.z:G.w;
        float b = (k==0)?B.x:(k==1)?B.y:(k==2)?B.z:B.w;
        float lr = srgb2lin(r), lg = srgb2lin(g), lb = srgb2lin(b);
        // RGB->XYZ with 1/WP folded into coefficients
        float X = 0.43395038f*lr + 0.37621015f*lg + 0.18984050f*lb;
        float Y = 0.21267290f*lr + 0.71515220f*lg + 0.07217500f*lb;
        float Z = 0.01775650f*lr + 0.10946790f*lg + 0.87277544f*lb;
        float fx = labf(X), fy = labf(Y), fz = labf(Z);
        float L = 116.0f * fy - 16.0f;
        ab[k] = __floats2half2_rn(500.0f * (fx - fy), 200.0f * (fy - fz));
        if (k==0) Lo.x=L; else if(k==1) Lo.y=L; else if (k==2) Lo.z=L; else Lo.w=L;
        vmin = fminf(vmin, L); vmax = fmaxf(vmax, L);
    }
    *(float4*)(g_L + p4) = Lo;
    *(uint2*)(g_ab + p4) = *(uint2*)ab;
    *(uint2*)(g_ab + p4 + 2) = *(uint2*)(ab + 2);

    #pragma unroll
    for (int o = 16; o > 0; o >>= 1) {
        vmin = fminf(vmin, __shfl_down_sync(0xFFFFFFFFu, vmin, o));
        vmax = fmaxf(vmax, __shfl_down_sync(0xFFFFFFFFu, vmax, o));
    }
    __shared__ float wmin[8], wmax[8];
    int lane = threadIdx.x & 31, warp = threadIdx.x >> 5;
    if (lane == 0) { wmin[warp] = vmin; wmax[warp] = vmax; }
    __syncthreads();
    if (threadIdx.x == 0) {
        float bmin = wmin[0], bmax = wmax[0];
        #pragma unroll
        for (int i = 1; i < 8; i++) {
            bmin = fminf(bmin, wmin[i]);
            bmax = fmaxf(bmax, wmax[i]);
        }
        g_blkmin[blockIdx.x] = bmin;
        g_blkmax[blockIdx.x] = bmax;
    }
}

// ---------------- K2: min/max finalize + quantize + tile hist (per-warp) + tile LUT ----
__global__ void k_quant_hist_lut() {
    int blk = blockIdx.x;
    int n = blk >> 6;
    int t = blk & 63;
    int ty = t >> 3, tx = t & 7;

    __shared__ int shw[8][NBINS];       // per-warp histograms
    __shared__ float wmin[8], wmax[8];
    __shared__ float ws8[8];
    __shared__ float s_lmin, s_scale, s_totc;

    // reduce this image's 256 per-block min/max (one value per thread)
    float vmin = g_blkmin[n * BLK_PER_IMG + threadIdx.x];
    float vmax = g_blkmax[n * BLK_PER_IMG + threadIdx.x];
    #pragma unroll
    for (int o = 16; o > 0; o >>= 1) {
        vmin = fminf(vmin, __shfl_down_sync(0xFFFFFFFFu, vmin, o));
        vmax = fmaxf(vmax, __shfl_down_sync(0xFFFFFFFFu, vmax, o));
    }
    int lane = threadIdx.x & 31, warp = threadIdx.x >> 5;
    if (lane == 0) { wmin[warp] = vmin; wmax[warp] = vmax; }
    #pragma unroll
    for (int w = 0; w < 8; w++) shw[w][threadIdx.x] = 0;
    __syncthreads();
    if (threadIdx.x == 0) {
        float bmin = wmin[0], bmax = wmax[0];
        #pragma unroll
        for (int i = 1; i < 8; i++) {
            bmin = fminf(bmin, wmin[i]);
            bmax = fmaxf(bmax, wmax[i]);
        }
        s_lmin = bmin;
        s_scale = 255.0f / (bmax - bmin + 1e-6f);
    }
    __syncthreads();

    float lmin = s_lmin, scale = s_scale;
    int* myh = shw[warp];
    int base = n * HW + (ty * TH) * WW + tx * TW;
    #pragma unroll
    for (int it = 0; it < 4; it++) {
        int i = threadIdx.x + it * 256;          // 0..1023 float4 chunks
        int row = i >> 4, c16 = i & 15;
        int p = base + row * WW + c16 * 4;
        float4 L4 = *(const float4*)(g_L + p);
        int v0 = min(max((int)rintf((L4.x - lmin) * scale), 0), 255);
        int v1 = min(max((int)rintf((L4.y - lmin) * scale), 0), 255);
        int v2 = min(max((int)rintf((L4.z - lmin) * scale), 0), 255);
        int v3 = min(max((int)rintf((L4.w - lmin) * scale), 0), 255);
        *(uchar4*)(g_lint + p) = make_uchar4((unsigned char)v0, (unsigned char)v1,
                                             (unsigned char)v2, (unsigned char)v3);
        atomicAdd(&myh[v0], 1);
        atomicAdd(&myh[v1], 1);
        atomicAdd(&myh[v2], 1);
        atomicAdd(&myh[v3], 1);
    }
    __syncthreads();

    int hist = 0;
    #pragma unroll
    for (int w = 0; w < 8; w++) hist += shw[w][threadIdx.x];
    g_tilehist[blk * NBINS + threadIdx.x] = hist;

    // CLAHE LUT for this tile, built in-place
    float clipped = fminf((float)hist, 32.0f);   // max(2.0*4096/256, 1.0)
    float cum = inclusive_scan_256(clipped, ws8);
    if (threadIdx.x == 255) s_totc = cum;
    __syncthreads();
    float excess = (float)AREA - s_totc;          // hist sums to exactly AREA
    float val = cum + (float)(threadIdx.x + 1) * (excess * (1.0f/256.0f));
    g_tilelut[blk * NBINS + threadIdx.x] = rintf(val * (255.0f / (float)AREA));
}

// ---------------- K3: equalize LUT per image -> precomputed (fy0, finv(fy0)) ----------------
__global__ void k_eqlut() {
    __shared__ float ws8[8];
    int n = blockIdx.x;
    int t = threadIdx.x;
    int s = 0;
    #pragma unroll
    for (int tt = 0; tt < NTILES; tt++)
        s += g_tilehist[(n * NTILES + tt) * NBINS + t];
    float cum = inclusive_scan_256((float)s, ws8);
    float eq_l = rintf(cum * (255.0f / (float)HW));
    float fy0 = fmaf(eq_l, 100.0f/(255.0f*116.0f), 16.0f/116.0f);
    g_eqlut2[n * NBINS + t] = make_float2(fy0, finv(fy0));
}

// ---------------- K4: reconstruct both outputs (4 px/thread) ----------------
__global__ void k_out(float* __restrict__ out) {
    int t  = blockIdx.x * blockDim.x + threadIdx.x;
    int p4 = t * 4;
    int n  = blockIdx.x / BLK_PER_IMG;
    int hw = p4 - n * HW;
    int h = hw >> 9, w0 = hw & 511;

    uchar4 v4 = *(const uchar4*)(g_lint + p4);
    uint4 abraw = *(const uint4*)(g_ab + p4);

    float cy = fminf(fmaxf(((float)h + 0.5f) * (1.0f/TH) - 0.5f, 0.0f), 7.0f);
    int   y0 = min((int)cy, GRIDN - 2);
    float wy = cy - (float)y0;

    const float*  lutn = g_tilelut + (size_t)n * NTILES * NBINS + y0 * (GRIDN * NBINS);
    const float2* eqn  = g_eqlut2 + n * NBINS;

    float4 R0, G0, Bl0, R1, G1, Bl1;
    #pragma unroll
    for (int k = 0; k < 4; k++) {
        int w = w0 + k;
        int v = (k==0)?v4.x:(k==1)?v4.y:(k==2)?v4.z:v4.w;
        unsigned int abu = (k==0)?abraw.x:(k==1)?abraw.y:(k==2)?abraw.z:abraw.w;
        float2 abf = __half22float2(*(__half2*)&abu);
        float a500 = abf.x * (1.0f/500.0f);
        float b200 = abf.y * (1.0f/200.0f);

        float2 eqv = eqn[v];                       // (fy0, finv(fy0))

        float cx = fminf(fmaxf(((float)w + 0.5f) * (1.0f/TW) - 0.5f, 0.0f), 7.0f);
        int   x0 = min((int)cx, GRIDN - 2);
        float wx = cx - (float)x0;
        const float* p00 = lutn + (x0 * NBINS + v);
        float v00 = p00[0];
        float v01 = p00[NBINS];
        float v10 = p00[GRIDN * NBINS];
        float v11 = p00[GRIDN * NBINS + NBINS];
        float top = v00 + (v01 - v00) * wx;
        float bot = v10 + (v11 - v10) * wx;
        float cl_l = top + (bot - top) * wy;

        // eq path: fy0/Y0 precomputed
        float fy0 = eqv.x;
        float Y0  = eqv.y;
        float X0 = finv(fy0 + a500);
        float Z0 = finv(fy0 - b200);
        // clahe path
        float fy1 = fmaf(cl_l, 100.0f/(255.0f*116.0f), 16.0f/116.0f);
        float X1 = finv(fy1 + a500);
        float Y1 = finv(fy1);
        float Z1 = finv(fy1 - b200);

        #define MRL(X,Y,Z) ( 3.0799546f*(X) - 1.5371385f*(Y) - 0.5428164f*(Z))
        #define MGL(X,Y,Z) (-0.9212582f*(X) + 1.8760108f*(Y) + 0.0452474f*(Z))
        #define MBL(X,Y,Z) ( 0.0528874f*(X) - 0.2040259f*(Y) + 1.1511382f*(Z))
        float r0 = srgb255(MRL(X0,Y0,Z0));
        float g0 = srgb255(MGL(X0,Y0,Z0));
        float b0 = srgb255(MBL(X0,Y0,Z0));
        float r1 = srgb255(MRL(X1,Y1,Z1));
        float g1 = srgb255(MGL(X1,Y1,Z1));
        float b1 = srgb255(MBL(X1,Y1,Z1));
        #undef MRL
        #undef MGL
        #undef MBL
        if (k==0){R0.x=r0;G0.x=g0;Bl0.x=b0;R1.x=r1;G1.x=g1;Bl1.x=b1;}
        else if (k==1){R0.y=r0;G0.y=g0;Bl0.y=b0;R1.y=r1;G1.y=g1;Bl1.y=b1;}
        else if (k==2){R0.z=r0;G0.z=g0;Bl0.z=b0;R1.z=r1;G1.z=g1;Bl1.z=b1;}
        else {R0.w=r0;G0.w=g0;Bl0.w=b0;R1.w=r1;G1.w=g1;Bl1.w=b1;}
    }

    size_t base0 = (size_t)n * 3 * HW + hw;        // equalize output
    size_t base1 = (size_t)NPIX * 3 + base0;       // clahe output
    *(float4*)(out + base0)          = R0;
    *(float4*)(out + base0 + HW)     = G0;
    *(float4*)(out + base0 + 2*HW)   = Bl0;
    *(float4*)(out + base1)          = R1;
    *(float4*)(out + base1 + HW)     = G1;
    *(float4*)(out + base1 + 2*HW)   = Bl1;
}

// ---------------- launch ----------------
extern "C" void kernel_launch(void* const* d_in, const int* in_sizes, int n_in,
                              void* d_out, int out_size) {
    const float* x = (const float*)d_in[0];
    float* out = (float*)d_out;
    (void)in_sizes; (void)n_in; (void)out_size;

    k_lab<<<LAB_BLOCKS, 256>>>(x);
    k_quant_hist_lut<<<N_IMG * NTILES, 256>>>();
    k_eqlut<<<N_IMG, NBINS>>>();
    k_out<<<LAB_BLOCKS, 256>>>(out);
}

// round 6
// speedup vs baseline: 2.9705x; 1.0139x over previous
#include <cuda_runtime.h>
#include <cuda_fp16.h>
#include <math.h>

#define N_IMG 16
#define HH 512
#define WW 512
#define HW (HH*WW)
#define NPIX (N_IMG*HW)
#define GRIDN 8
#define TH 64
#define TW 64
#define AREA (TH*TW)
#define NBINS 256
#define NTILES (GRIDN*GRIDN)
#define LAB_BLOCKS (NPIX/4/256)          // 4096
#define BLK_PER_IMG (LAB_BLOCKS/N_IMG)   // 256

#define LAB_EPS (216.0f/24389.0f)
#define LAB_KAPPA (24389.0f/27.0f)

// ---------------- scratch (no allocations allowed) ----------------
__device__ float   g_L[NPIX];
__device__ __half2 g_ab[NPIX];
__device__ unsigned char g_lint[NPIX];
__device__ float g_blkmin[LAB_BLOCKS];
__device__ float g_blkmax[LAB_BLOCKS];
__device__ int    g_tilehist[N_IMG*NTILES*NBINS];
__device__ float  g_tilelut [N_IMG*NTILES*NBINS];
__device__ float2 g_eqlut2  [N_IMG*NBINS];   // (fy0, finv(fy0)) per bin
__device__ int2   g_cxlut   [WW];            // (wx bits, x0*NBINS) per column

// ---------------- MUFU primitives ----------------
__device__ __forceinline__ float ex2f(float x){ float r; asm("ex2.approx.f32 %0, %1;" : "=f"(r) : "f"(x)); return r; }
__device__ __forceinline__ float lg2f(float x){ float r; asm("lg2.approx.f32 %0, %1;" : "=f"(r) : "f"(x)); return r; }

// ---------------- packed f32x2 primitives ----------------
#define C2(c) make_float2((c), (c))
__device__ __forceinline__ float2 f2mul(float2 a, float2 b){
    float2 r;
    asm("{\n\t.reg .b64 A,B,R;\n\tmov.b64 A,{%2,%3};\n\tmov.b64 B,{%4,%5};\n\t"
        "mul.rn.f32x2 R,A,B;\n\tmov.b64 {%0,%1},R;\n\t}"
        : "=f"(r.x), "=f"(r.y)
        : "f"(a.x), "f"(a.y), "f"(b.x), "f"(b.y));
    return r;
}
__device__ __forceinline__ float2 f2add(float2 a, float2 b){
    float2 r;
    asm("{\n\t.reg .b64 A,B,R;\n\tmov.b64 A,{%2,%3};\n\tmov.b64 B,{%4,%5};\n\t"
        "add.rn.f32x2 R,A,B;\n\tmov.b64 {%0,%1},R;\n\t}"
        : "=f"(r.x), "=f"(r.y)
        : "f"(a.x), "f"(a.y), "f"(b.x), "f"(b.y));
    return r;
}
__device__ __forceinline__ float2 f2fma(float2 a, float2 b, float2 c){
    float2 r;
    asm("{\n\t.reg .b64 A,B,Cc,R;\n\tmov.b64 A,{%2,%3};\n\tmov.b64 B,{%4,%5};\n\t"
        "mov.b64 Cc,{%6,%7};\n\tfma.rn.f32x2 R,A,B,Cc;\n\tmov.b64 {%0,%1},R;\n\t}"
        : "=f"(r.x), "=f"(r.y)
        : "f"(a.x), "f"(a.y), "f"(b.x), "f"(b.y), "f"(c.x), "f"(c.y));
    return r;
}

// ---------------- packed helpers ----------------
__device__ __forceinline__ float2 srgb2lin2(float2 c) {
    float2 lin = f2mul(c, C2(1.0f/12.92f));
    float2 t = f2fma(c, C2(1.0f/1.055f), C2(0.055f/1.055f));
    float2 e = f2mul(make_float2(lg2f(t.x), lg2f(t.y)), C2(2.4f));
    float px = ex2f(e.x), py = ex2f(e.y);
    float2 r;
    r.x = (c.x <= 0.04045f) ? lin.x : px;
    r.y = (c.y <= 0.04045f) ? lin.y : py;
    return r;
}
__device__ __forceinline__ float2 labf2(float2 x) {
    float2 lin = f2fma(x, C2(LAB_KAPPA/116.0f), C2(16.0f/116.0f));
    float2 e = f2mul(make_float2(lg2f(x.x), lg2f(x.y)), C2(1.0f/3.0f));
    float px = ex2f(e.x), py = ex2f(e.y);
    float2 r;
    r.x = (x.x > LAB_EPS) ? px : lin.x;
    r.y = (x.y > LAB_EPS) ? py : lin.y;
    return r;
}
__device__ __forceinline__ float finv(float f) {
    float f3 = f * f * f;
    float lin = fmaf(f, 116.0f/LAB_KAPPA, -16.0f/LAB_KAPPA);
    return (f3 > LAB_EPS) ? f3 : lin;
}
__device__ __forceinline__ float2 finv2(float2 f) {
    float2 t  = f2mul(f, f);
    float2 f3 = f2mul(t, f);
    float2 lin = f2fma(f, C2(116.0f/LAB_KAPPA), C2(-16.0f/LAB_KAPPA));
    float2 r;
    r.x = (f3.x > LAB_EPS) ? f3.x : lin.x;
    r.y = (f3.y > LAB_EPS) ? f3.y : lin.y;
    return r;
}
// 255 * clip(lin2srgb(c),0,1), packed pair
__device__ __forceinline__ float2 srgb255_2(float2 c) {
    float2 lin = f2mul(c, C2(12.92f * 255.0f));
    float2 e = f2fma(make_float2(lg2f(c.x), lg2f(c.y)), C2(1.0f/2.4f), C2(8.0715942f));
    float2 p = f2add(make_float2(ex2f(e.x), ex2f(e.y)), C2(-14.025f));
    float rx = (c.x <= 0.0031308f) ? lin.x : p.x;
    float ry = (c.y <= 0.0031308f) ? lin.y : p.y;
    rx = fminf(fmaxf(rx, 0.0f), 255.0f);
    ry = fminf(fmaxf(ry, 0.0f), 255.0f);
    return make_float2(rx, ry);
}

__device__ __forceinline__ float inclusive_scan_256(float v, float* ws8) {
    int lane = threadIdx.x & 31, warp = threadIdx.x >> 5;
    #pragma unroll
    for (int o = 1; o < 32; o <<= 1) {
        float t = __shfl_up_sync(0xFFFFFFFFu, v, o);
        if (lane >= o) v += t;
    }
    if (lane == 31) ws8[warp] = v;
    __syncthreads();
    if (warp == 0 && lane < 8) {
        float s = ws8[lane];
        #pragma unroll
        for (int o = 1; o < 8; o <<= 1) {
            float t = __shfl_up_sync(0xFFu, s, o);
            if (lane >= o) s += t;
        }
        ws8[lane] = s;
    }
    __syncthreads();
    if (warp > 0) v += ws8[warp - 1];
    return v;
}

// ---------------- K1: RGB -> Lab (packed pixel pairs) + per-block min/max ----------------
__global__ void k_lab(const float* __restrict__ x) {
    int t  = blockIdx.x * blockDim.x + threadIdx.x;
    int p4 = t * 4;
    int n  = blockIdx.x / BLK_PER_IMG;
    int hw = p4 - n * HW;
    const float* img = x + (size_t)n * 3 * HW;
    float4 R = *(const float4*)(img + hw);
    float4 G = *(const float4*)(img + HW + hw);
    float4 B = *(const float4*)(img + 2*HW + hw);
    const float* Rf = (const float*)&R;
    const float* Gf = (const float*)&G;
    const float* Bf = (const float*)&B;

    float Lo[4];
    __half2 ab[4];
    float vmin =  1e30f, vmax = -1e30f;
    #pragma unroll
    for (int q = 0; q < 2; q++) {
        float2 r = make_float2(Rf[2*q], Rf[2*q+1]);
        float2 g = make_float2(Gf[2*q], Gf[2*q+1]);
        float2 b = make_float2(Bf[2*q], Bf[2*q+1]);
        float2 lr = srgb2lin2(r), lg = srgb2lin2(g), lb = srgb2lin2(b);
        // RGB->XYZ with 1/WP folded into coefficients
        float2 X = f2mul(lr, C2(0.43395038f));
        X = f2fma(lg, C2(0.37621015f), X);
        X = f2fma(lb, C2(0.18984050f), X);
        float2 Y = f2mul(lr, C2(0.21267290f));
        Y = f2fma(lg, C2(0.71515220f), Y);
        Y = f2fma(lb, C2(0.07217500f), Y);
        float2 Z = f2mul(lr, C2(0.01775650f));
        Z = f2fma(lg, C2(0.10946790f), Z);
        Z = f2fma(lb, C2(0.87277544f), Z);
        float2 fx = labf2(X), fy = labf2(Y), fz = labf2(Z);
        float2 L = f2fma(fy, C2(116.0f), C2(-16.0f));
        float2 A = f2fma(fy, C2(-500.0f), f2mul(fx, C2(500.0f)));
        float2 Bv= f2fma(fz, C2(-200.0f), f2mul(fy, C2(200.0f)));
        Lo[2*q] = L.x; Lo[2*q+1] = L.y;
        ab[2*q]   = __floats2half2_rn(A.x, Bv.x);
        ab[2*q+1] = __floats2half2_rn(A.y, Bv.y);
        vmin = fminf(vmin, fminf(L.x, L.y));
        vmax = fmaxf(vmax, fmaxf(L.x, L.y));
    }
    *(float4*)(g_L + p4) = *(float4*)Lo;
    *(uint2*)(g_ab + p4) = *(uint2*)ab;
    *(uint2*)(g_ab + p4 + 2) = *(uint2*)(ab + 2);

    #pragma unroll
    for (int o = 16; o > 0; o >>= 1) {
        vmin = fminf(vmin, __shfl_down_sync(0xFFFFFFFFu, vmin, o));
        vmax = fmaxf(vmax, __shfl_down_sync(0xFFFFFFFFu, vmax, o));
    }
    __shared__ float wmin[8], wmax[8];
    int lane = threadIdx.x & 31, warp = threadIdx.x >> 5;
    if (lane == 0) { wmin[warp] = vmin; wmax[warp] = vmax; }
    __syncthreads();
    if (threadIdx.x == 0) {
        float bmin = wmin[0], bmax = wmax[0];
        #pragma unroll
        for (int i = 1; i < 8; i++) {
            bmin = fminf(bmin, wmin[i]);
            bmax = fmaxf(bmax, wmax[i]);
        }
        g_blkmin[blockIdx.x] = bmin;
        g_blkmax[blockIdx.x] = bmax;
    }
}

// ---------------- K2: min/max finalize + quantize + tile hist (per-warp) + tile LUT ----
__global__ void k_quant_hist_lut() {
    int blk = blockIdx.x;
    int n = blk >> 6;
    int t = blk & 63;
    int ty = t >> 3, tx = t & 7;

    __shared__ int shw[8][NBINS];       // per-warp histograms
    __shared__ float wmin[8], wmax[8];
    __shared__ float ws8[8];
    __shared__ float s_lmin, s_scale, s_totc;

    float vmin = g_blkmin[n * BLK_PER_IMG + threadIdx.x];
    float vmax = g_blkmax[n * BLK_PER_IMG + threadIdx.x];
    #pragma unroll
    for (int o = 16; o > 0; o >>= 1) {
        vmin = fminf(vmin, __shfl_down_sync(0xFFFFFFFFu, vmin, o));
        vmax = fmaxf(vmax, __shfl_down_sync(0xFFFFFFFFu, vmax, o));
    }
    int lane = threadIdx.x & 31, warp = threadIdx.x >> 5;
    if (lane == 0) { wmin[warp] = vmin; wmax[warp] = vmax; }
    #pragma unroll
    for (int w = 0; w < 8; w++) shw[w][threadIdx.x] = 0;
    __syncthreads();
    if (threadIdx.x == 0) {
        float bmin = wmin[0], bmax = wmax[0];
        #pragma unroll
        for (int i = 1; i < 8; i++) {
            bmin = fminf(bmin, wmin[i]);
            bmax = fmaxf(bmax, wmax[i]);
        }
        s_lmin = bmin;
        s_scale = 255.0f / (bmax - bmin + 1e-6f);
    }
    __syncthreads();

    float lmin = s_lmin, scale = s_scale;
    int* myh = shw[warp];
    int base = n * HW + (ty * TH) * WW + tx * TW;
    #pragma unroll
    for (int it = 0; it < 4; it++) {
        int i = threadIdx.x + it * 256;          // 0..1023 float4 chunks
        int row = i >> 4, c16 = i & 15;
        int p = base + row * WW + c16 * 4;
        float4 L4 = *(const float4*)(g_L + p);
        int v0 = min(max((int)rintf((L4.x - lmin) * scale), 0), 255);
        int v1 = min(max((int)rintf((L4.y - lmin) * scale), 0), 255);
        int v2 = min(max((int)rintf((L4.z - lmin) * scale), 0), 255);
        int v3 = min(max((int)rintf((L4.w - lmin) * scale), 0), 255);
        *(uchar4*)(g_lint + p) = make_uchar4((unsigned char)v0, (unsigned char)v1,
                                             (unsigned char)v2, (unsigned char)v3);
        atomicAdd(&myh[v0], 1);
        atomicAdd(&myh[v1], 1);
        atomicAdd(&myh[v2], 1);
        atomicAdd(&myh[v3], 1);
    }
    __syncthreads();

    int hist = 0;
    #pragma unroll
    for (int w = 0; w < 8; w++) hist += shw[w][threadIdx.x];
    g_tilehist[blk * NBINS + threadIdx.x] = hist;

    float clipped = fminf((float)hist, 32.0f);   // max(2.0*4096/256, 1.0)
    float cum = inclusive_scan_256(clipped, ws8);
    if (threadIdx.x == 255) s_totc = cum;
    __syncthreads();
    float excess = (float)AREA - s_totc;          // hist sums to exactly AREA
    float val = cum + (float)(threadIdx.x + 1) * (excess * (1.0f/256.0f));
    g_tilelut[blk * NBINS + threadIdx.x] = rintf(val * (255.0f / (float)AREA));
}

// ---------------- K3: equalize LUT (fy0, finv(fy0)) + per-column cx LUT ----------------
__global__ void k_eqlut() {
    __shared__ float ws8[8];
    int n = blockIdx.x;
    int t = threadIdx.x;
    int s = 0;
    #pragma unroll
    for (int tt = 0; tt < NTILES; tt++)
        s += g_tilehist[(n * NTILES + tt) * NBINS + t];
    float cum = inclusive_scan_256((float)s, ws8);
    float eq_l = rintf(cum * (255.0f / (float)HW));
    float fy0 = fmaf(eq_l, 100.0f/(255.0f*116.0f), 16.0f/116.0f);
    g_eqlut2[n * NBINS + t] = make_float2(fy0, finv(fy0));

    if (n == 0) {
        #pragma unroll
        for (int w = t; w < WW; w += 256) {
            float cx = fminf(fmaxf(((float)w + 0.5f) * (1.0f/TW) - 0.5f, 0.0f), 7.0f);
            int x0 = min((int)cx, GRIDN - 2);
            float wx = cx - (float)x0;
            g_cxlut[w] = make_int2(__float_as_int(wx), x0 * NBINS);
        }
    }
}

// ---------------- K4: reconstruct both outputs (4 px/thread, f32x2 dual path) ----------
__global__ void k_out(float* __restrict__ out) {
    int t  = blockIdx.x * blockDim.x + threadIdx.x;
    int p4 = t * 4;
    int n  = blockIdx.x / BLK_PER_IMG;
    int hw = p4 - n * HW;
    int h = hw >> 9, w0 = hw & 511;

    uchar4 v4 = *(const uchar4*)(g_lint + p4);
    uint4 abraw = *(const uint4*)(g_ab + p4);

    float cy = fminf(fmaxf(((float)h + 0.5f) * (1.0f/TH) - 0.5f, 0.0f), 7.0f);
    int   y0 = min((int)cy, GRIDN - 2);
    float wy = cy - (float)y0;

    const float*  lutn = g_tilelut + (size_t)n * NTILES * NBINS + y0 * (GRIDN * NBINS);
    const float2* eqn  = g_eqlut2 + n * NBINS;

    float R0[4], G0[4], B0[4], R1[4], G1[4], B1[4];
    #pragma unroll
    for (int k = 0; k < 4; k++) {
        int w = w0 + k;
        int v = (k==0)?v4.x:(k==1)?v4.y:(k==2)?v4.z:v4.w;
        unsigned int abu = (k==0)?abraw.x:(k==1)?abraw.y:(k==2)?abraw.z:abraw.w;
        float2 abf = __half22float2(*(__half2*)&abu);
        float a500  = abf.x * (1.0f/500.0f);
        float nb200 = abf.y * (-1.0f/200.0f);

        float2 eqv = eqn[v];                       // (fy0, finv(fy0))

        int2 cxe = g_cxlut[w];
        float wx = __int_as_float(cxe.x);
        const float* p00 = lutn + cxe.y + v;
        float v00 = p00[0];
        float v01 = p00[NBINS];
        float v10 = p00[GRIDN * NBINS];
        float v11 = p00[GRIDN * NBINS + NBINS];
        float top = fmaf(wx, v01 - v00, v00);
        float bot = fmaf(wx, v11 - v10, v10);
        float cl_l = fmaf(wy, bot - top, top);

        // packed (eq, clahe) lanes
        float fy1 = fmaf(cl_l, 100.0f/(255.0f*116.0f), 16.0f/116.0f);
        float2 fy01 = make_float2(eqv.x, fy1);
        float2 fx = f2add(fy01, make_float2(a500, a500));
        float2 fz = f2add(fy01, make_float2(nb200, nb200));
        float2 X = finv2(fx);
        float2 Z = finv2(fz);
        float2 Y = make_float2(eqv.y, finv(fy1));

        float2 rl = f2mul(X, C2(3.0799546f));
        rl = f2fma(Y, C2(-1.5371385f), rl);
        rl = f2fma(Z, C2(-0.5428164f), rl);
        float2 gl = f2mul(X, C2(-0.9212582f));
        gl = f2fma(Y, C2(1.8760108f), gl);
        gl = f2fma(Z, C2(0.0452474f), gl);
        float2 bl = f2mul(X, C2(0.0528874f));
        bl = f2fma(Y, C2(-0.2040259f), bl);
        bl = f2fma(Z, C2(1.1511382f), bl);

        float2 rp = srgb255_2(rl);
        float2 gp = srgb255_2(gl);
        float2 bp = srgb255_2(bl);
        R0[k] = rp.x; R1[k] = rp.y;
        G0[k] = gp.x; G1[k] = gp.y;
        B0[k] = bp.x; B1[k] = bp.y;
    }

    size_t base0 = (size_t)n * 3 * HW + hw;        // equalize output
    size_t base1 = (size_t)NPIX * 3 + base0;       // clahe output
    *(float4*)(out + base0)          = *(float4*)R0;
    *(float4*)(out + base0 + HW)     = *(float4*)G0;
    *(float4*)(out + base0 + 2*HW)   = *(float4*)B0;
    *(float4*)(out + base1)          = *(float4*)R1;
    *(float4*)(out + base1 + HW)     = *(float4*)G1;
    *(float4*)(out + base1 + 2*HW)   = *(float4*)B1;
}

// ---------------- launch ----------------
extern "C" void kernel_launch(void* const* d_in, const int* in_sizes, int n_in,
                              void* d_out, int out_size) {
    const float* x = (const float*)d_in[0];
    float* out = (float*)d_out;
    (void)in_sizes; (void)n_in; (void)out_size;

    k_lab<<<LAB_BLOCKS, 256>>>(x);
    k_quant_hist_lut<<<N_IMG * NTILES, 256>>>();
    k_eqlut<<<N_IMG, NBINS>>>();
    k_out<<<LAB_BLOCKS, 256>>>(out);
}